// round 9
// baseline (speedup 1.0000x reference)
#include <cuda_runtime.h>
#include <cstdint>

#define NUM_GRAPHS 16384
#define EMB_DIM 128
#define NCTA 1216            // ~8 CTAs/SM on 152 SMs
#define MAX_G_PER_CTA 16     // ceil(16384/1216)=14, padded

// Precomputed segment boundaries (lower_bound of each graph id).
__device__ int g_offs_atoms[NUM_GRAPHS + 1];
__device__ int g_offs_frags[NUM_GRAPHS + 1];

__device__ __forceinline__ int idx_at(const void* __restrict__ b, int i, bool is64) {
    if (is64) return (int)(((const long long* __restrict__)b)[i]);
    return ((const int* __restrict__)b)[i];
}

// Ids sorted in [0,16384). As int32, position n-1 (odd) is an int64 high word
// => 0 under int64 layout; nonzero (largest id) under int32 layout.
__device__ __forceinline__ bool detect_is64(const void* __restrict__ b, int n) {
    return ((const int* __restrict__)b)[n - 1] == 0;
}

// Fused vectorized prologue: one launch covers both index arrays.
__global__ void build_offsets_fused(const void* __restrict__ a, int na, int* __restrict__ offsA,
                                    const void* __restrict__ f, int nf, int* __restrict__ offsF) {
    const int chunksA = (na + 7) >> 3;
    const int chunksF = (nf + 7) >> 3;
    const int total   = chunksA + chunksF;
    const int stride  = gridDim.x * blockDim.x;

    for (int c = blockIdx.x * blockDim.x + threadIdx.x; c < total; c += stride) {
        const bool isF = (c >= chunksA);
        const void* __restrict__ b = isF ? f : a;
        const int n = isF ? nf : na;
        int* __restrict__ offs = isF ? offsF : offsA;
        const int base = (isF ? (c - chunksA) : c) << 3;
        const bool is64 = detect_is64(b, n);

        int ids[8];
        if (base + 8 <= n) {
            if (is64) {
                const ulonglong2* p = (const ulonglong2*)((const long long*)b + base);
                ulonglong2 v0 = __ldcg(p), v1 = __ldcg(p + 1), v2 = __ldcg(p + 2), v3 = __ldcg(p + 3);
                ids[0] = (int)v0.x; ids[1] = (int)v0.y;
                ids[2] = (int)v1.x; ids[3] = (int)v1.y;
                ids[4] = (int)v2.x; ids[5] = (int)v2.y;
                ids[6] = (int)v3.x; ids[7] = (int)v3.y;
            } else {
                const int4* p = (const int4*)((const int*)b + base);
                int4 v0 = __ldcg(p), v1 = __ldcg(p + 1);
                ids[0] = v0.x; ids[1] = v0.y; ids[2] = v0.z; ids[3] = v0.w;
                ids[4] = v1.x; ids[5] = v1.y; ids[6] = v1.z; ids[7] = v1.w;
            }
            int prev = (base == 0) ? -1 : idx_at(b, base - 1, is64);
            #pragma unroll
            for (int j = 0; j < 8; j++) {
                const int cur = ids[j];
                if (cur != prev) {
                    for (int id = prev + 1; id <= cur; ++id) offs[id] = base + j;
                    prev = cur;
                }
            }
            if (base + 8 == n) {
                for (int id = ids[7] + 1; id <= NUM_GRAPHS; ++id) offs[id] = n;
            }
        } else {
            int prev = (base == 0) ? -1 : idx_at(b, base - 1, is64);
            for (int i = base; i < n; i++) {
                const int cur = idx_at(b, i, is64);
                for (int id = prev + 1; id <= cur; ++id) offs[id] = i;
                prev = cur;
                if (i == n - 1) {
                    for (int id = cur + 1; id <= NUM_GRAPHS; ++id) offs[id] = n;
                }
            }
        }
    }
}

__device__ __forceinline__ void acc_add(float4& a, const float4& v) {
    a.x += v.x; a.y += v.y; a.z += v.z; a.w += v.w;
}

// Persistent CTA-per-graph-range pooling. CTA c owns a CONTIGUOUS range of
// ~13-14 graphs => its input accesses form one dense forward stream per array.
// Inside a graph: warps stride rows by 4, each lane one float4 => full 512B
// row per warp-iteration (coalesced LDG.128, L1-bypass), unroll 4 for MLP.
// Per-CTA bounds slice is staged in shared once; per-graph boundary reads are
// LDS hits.
__global__ __launch_bounds__(128, 8)
void fragnet_pool_kernel(const float* __restrict__ x_atoms,
                         const float* __restrict__ x_frags,
                         float* __restrict__ out) {
    const int c    = blockIdx.x;
    const int warp = threadIdx.x >> 5;
    const int lane = threadIdx.x & 31;

    const int g0 = (int)(((long long)c * NUM_GRAPHS) / NCTA);
    const int g1 = (int)(((long long)(c + 1) * NUM_GRAPHS) / NCTA);
    const int ng = g1 - g0;                 // <= 14

    __shared__ int sA[MAX_G_PER_CTA + 1];
    __shared__ int sF[MAX_G_PER_CTA + 1];
    __shared__ float4 shA[4][32];
    __shared__ float4 shF[4][32];

    // Stage the bounds slice once (two warps load concurrently).
    if (threadIdx.x <= ng)                        sA[threadIdx.x]      = g_offs_atoms[g0 + threadIdx.x];
    if (threadIdx.x >= 32 && threadIdx.x - 32 <= ng) sF[threadIdx.x - 32] = g_offs_frags[g0 + threadIdx.x - 32];
    __syncthreads();

    for (int i = 0; i < ng; ++i) {
        const int a_start = sA[i], a_end = sA[i + 1];
        const int f_start = sF[i], f_end = sF[i + 1];

        float4 accA0 = make_float4(0.f, 0.f, 0.f, 0.f);
        float4 accA1 = make_float4(0.f, 0.f, 0.f, 0.f);
        float4 accF  = make_float4(0.f, 0.f, 0.f, 0.f);

        // Atoms
        {
            int r = a_start + warp;
            for (; r + 12 < a_end; r += 16) {
                float4 v0 = __ldcg(reinterpret_cast<const float4*>(x_atoms + (size_t)r * EMB_DIM) + lane);
                float4 v1 = __ldcg(reinterpret_cast<const float4*>(x_atoms + (size_t)(r + 4) * EMB_DIM) + lane);
                float4 v2 = __ldcg(reinterpret_cast<const float4*>(x_atoms + (size_t)(r + 8) * EMB_DIM) + lane);
                float4 v3 = __ldcg(reinterpret_cast<const float4*>(x_atoms + (size_t)(r + 12) * EMB_DIM) + lane);
                acc_add(accA0, v0); acc_add(accA1, v1);
                acc_add(accA0, v2); acc_add(accA1, v3);
            }
            for (; r < a_end; r += 4) {
                float4 v = __ldcg(reinterpret_cast<const float4*>(x_atoms + (size_t)r * EMB_DIM) + lane);
                acc_add(accA0, v);
            }
        }
        // Frags
        {
            int r = f_start + warp;
            for (; r + 4 < f_end; r += 8) {
                float4 v0 = __ldcg(reinterpret_cast<const float4*>(x_frags + (size_t)r * EMB_DIM) + lane);
                float4 v1 = __ldcg(reinterpret_cast<const float4*>(x_frags + (size_t)(r + 4) * EMB_DIM) + lane);
                acc_add(accF, v0); acc_add(accF, v1);
            }
            if (r < f_end) {
                float4 v = __ldcg(reinterpret_cast<const float4*>(x_frags + (size_t)r * EMB_DIM) + lane);
                acc_add(accF, v);
            }
        }

        acc_add(accA0, accA1);
        shA[warp][lane] = accA0;
        shF[warp][lane] = accF;
        __syncthreads();

        // Warp 0 reduces+writes atoms half, warp 1 frags half.
        if (warp < 2) {
            const float4 (*sh)[32] = (warp == 0) ? shA : shF;
            float4 a0 = sh[0][lane], a1 = sh[1][lane], a2 = sh[2][lane], a3 = sh[3][lane];
            float4 s = make_float4(a0.x + a1.x + a2.x + a3.x,
                                   a0.y + a1.y + a2.y + a3.y,
                                   a0.z + a1.z + a2.z + a3.z,
                                   a0.w + a1.w + a2.w + a3.w);
            reinterpret_cast<float4*>(out + (size_t)(g0 + i) * (2 * EMB_DIM) + warp * EMB_DIM)[lane] = s;
        }
        __syncthreads();   // shared reduce buffers reused next graph
    }
}

extern "C" void kernel_launch(void* const* d_in, const int* in_sizes, int n_in,
                              void* d_out, int out_size) {
    const float* x_atoms    = (const float*)d_in[0];
    const float* x_frags    = (const float*)d_in[1];
    const void*  batch      = d_in[2];
    const void*  frag_batch = d_in[3];
    float* out = (float*)d_out;

    const int n_atoms = in_sizes[2];
    const int n_frags = in_sizes[3];

    int* offs_atoms = nullptr;
    int* offs_frags = nullptr;
    cudaGetSymbolAddress((void**)&offs_atoms, g_offs_atoms);
    cudaGetSymbolAddress((void**)&offs_frags, g_offs_frags);

    const int chunks = ((n_atoms + 7) >> 3) + ((n_frags + 7) >> 3);
    const int T = 256;
    build_offsets_fused<<<(chunks + T - 1) / T, T>>>(batch, n_atoms, offs_atoms,
                                                     frag_batch, n_frags, offs_frags);
    fragnet_pool_kernel<<<NCTA, 128>>>(x_atoms, x_frags, out);
}

// round 11
// speedup vs baseline: 1.0946x; 1.0946x over previous
#include <cuda_runtime.h>
#include <cstdint>

#define NUM_GRAPHS 16384
#define EMB_DIM 128

// Precomputed segment boundaries (lower_bound of each graph id).
__device__ int g_offs_atoms[NUM_GRAPHS + 1];
__device__ int g_offs_frags[NUM_GRAPHS + 1];

__device__ __forceinline__ int idx_at(const void* __restrict__ b, int i, bool is64) {
    if (is64) return (int)(((const long long* __restrict__)b)[i]);
    return ((const int* __restrict__)b)[i];
}

// Ids sorted in [0,16384). As int32, position n-1 (odd) is an int64 high word
// => 0 under int64 layout; nonzero (largest id) under int32 layout.
__device__ __forceinline__ bool detect_is64(const void* __restrict__ b, int n) {
    return ((const int* __restrict__)b)[n - 1] == 0;
}

// Fused vectorized prologue, 16 elements per thread (4x int4 or 8x ulonglong2
// in flight) to beat the latency wall seen at 8 elems/thread.
__global__ void build_offsets_fused(const void* __restrict__ a, int na, int* __restrict__ offsA,
                                    const void* __restrict__ f, int nf, int* __restrict__ offsF) {
    const int chunksA = (na + 15) >> 4;
    const int chunksF = (nf + 15) >> 4;
    const int total   = chunksA + chunksF;
    const int stride  = gridDim.x * blockDim.x;

    for (int c = blockIdx.x * blockDim.x + threadIdx.x; c < total; c += stride) {
        const bool isF = (c >= chunksA);
        const void* __restrict__ b = isF ? f : a;
        const int n = isF ? nf : na;
        int* __restrict__ offs = isF ? offsF : offsA;
        const int base = (isF ? (c - chunksA) : c) << 4;
        const bool is64 = detect_is64(b, n);

        int ids[16];
        if (base + 16 <= n) {
            if (is64) {
                const ulonglong2* p = (const ulonglong2*)((const long long*)b + base);
                ulonglong2 w0 = __ldcg(p),     w1 = __ldcg(p + 1), w2 = __ldcg(p + 2), w3 = __ldcg(p + 3);
                ulonglong2 w4 = __ldcg(p + 4), w5 = __ldcg(p + 5), w6 = __ldcg(p + 6), w7 = __ldcg(p + 7);
                ids[0]  = (int)w0.x; ids[1]  = (int)w0.y; ids[2]  = (int)w1.x; ids[3]  = (int)w1.y;
                ids[4]  = (int)w2.x; ids[5]  = (int)w2.y; ids[6]  = (int)w3.x; ids[7]  = (int)w3.y;
                ids[8]  = (int)w4.x; ids[9]  = (int)w4.y; ids[10] = (int)w5.x; ids[11] = (int)w5.y;
                ids[12] = (int)w6.x; ids[13] = (int)w6.y; ids[14] = (int)w7.x; ids[15] = (int)w7.y;
            } else {
                const int4* p = (const int4*)((const int*)b + base);
                int4 v0 = __ldcg(p), v1 = __ldcg(p + 1), v2 = __ldcg(p + 2), v3 = __ldcg(p + 3);
                ids[0]  = v0.x; ids[1]  = v0.y; ids[2]  = v0.z; ids[3]  = v0.w;
                ids[4]  = v1.x; ids[5]  = v1.y; ids[6]  = v1.z; ids[7]  = v1.w;
                ids[8]  = v2.x; ids[9]  = v2.y; ids[10] = v2.z; ids[11] = v2.w;
                ids[12] = v3.x; ids[13] = v3.y; ids[14] = v3.z; ids[15] = v3.w;
            }
            int prev = (base == 0) ? -1 : idx_at(b, base - 1, is64);
            #pragma unroll
            for (int j = 0; j < 16; j++) {
                const int cur = ids[j];
                if (cur != prev) {
                    for (int id = prev + 1; id <= cur; ++id) offs[id] = base + j;
                    prev = cur;
                }
            }
            if (base + 16 == n) {
                for (int id = ids[15] + 1; id <= NUM_GRAPHS; ++id) offs[id] = n;
            }
        } else {
            int prev = (base == 0) ? -1 : idx_at(b, base - 1, is64);
            for (int i = base; i < n; i++) {
                const int cur = idx_at(b, i, is64);
                for (int id = prev + 1; id <= cur; ++id) offs[id] = i;
                prev = cur;
                if (i == n - 1) {
                    for (int id = cur + 1; id <= NUM_GRAPHS; ++id) offs[id] = n;
                }
            }
        }
    }
}

__device__ __forceinline__ float4 f4_add(const float4& a, const float4& b) {
    return make_float4(a.x + b.x, a.y + b.y, a.z + b.z, a.w + b.w);
}

// One-shot CTA-per-graph pooling (R3 skeleton): warps stride rows by 4, each
// lane one float4 => full 512B row per warp-iteration (coalesced LDG.128,
// L1-bypass), unroll 4 for MLP. Reg-slimmed (single acc, pairwise adds,
// pointer increments) to fit 9 CTAs/SM.
__global__ __launch_bounds__(128, 9)
void fragnet_pool_kernel(const float* __restrict__ x_atoms,
                         const float* __restrict__ x_frags,
                         float* __restrict__ out) {
    const int g    = blockIdx.x;
    const int warp = threadIdx.x >> 5;
    const int lane = threadIdx.x & 31;

    __shared__ int bounds[4];          // [a_start, a_end, f_start, f_end]
    __shared__ float4 shA[4][32];
    __shared__ float4 shF[4][32];

    if (threadIdx.x < 4) {
        const int* offs = (threadIdx.x >= 2) ? g_offs_frags : g_offs_atoms;
        bounds[threadIdx.x] = offs[g + (threadIdx.x & 1)];
    }
    __syncthreads();

    const int a_start = bounds[0], a_end = bounds[1];
    const int f_start = bounds[2], f_end = bounds[3];

    float4 accA = make_float4(0.f, 0.f, 0.f, 0.f);
    float4 accF = make_float4(0.f, 0.f, 0.f, 0.f);

    // Atoms: unroll 4 rows (one row = 32 float4; warp stride 4 rows = 128 float4).
    {
        int nrows = a_end - (a_start + warp);              // rows this warp touches, stride 4
        const float4* p = reinterpret_cast<const float4*>(x_atoms + (size_t)(a_start + warp) * EMB_DIM) + lane;
        while (nrows > 12) {                               // 4 strided rows available
            float4 v0 = __ldcg(p);
            float4 v1 = __ldcg(p + 128);
            float4 v2 = __ldcg(p + 256);
            float4 v3 = __ldcg(p + 384);
            p += 512;
            nrows -= 16;
            accA = f4_add(accA, f4_add(f4_add(v0, v1), f4_add(v2, v3)));
        }
        while (nrows > 0) {
            float4 v = __ldcg(p);
            p += 128;
            nrows -= 4;
            accA = f4_add(accA, v);
        }
    }
    // Frags: unroll 2 (segments are half the size).
    {
        int nrows = f_end - (f_start + warp);
        const float4* p = reinterpret_cast<const float4*>(x_frags + (size_t)(f_start + warp) * EMB_DIM) + lane;
        while (nrows > 4) {
            float4 v0 = __ldcg(p);
            float4 v1 = __ldcg(p + 128);
            p += 256;
            nrows -= 8;
            accF = f4_add(accF, f4_add(v0, v1));
        }
        if (nrows > 0) {
            float4 v = __ldcg(p);
            accF = f4_add(accF, v);
        }
    }

    shA[warp][lane] = accA;
    shF[warp][lane] = accF;
    __syncthreads();

    // Warp 0 reduces+writes the atoms half, warp 1 the frags half.
    if (warp < 2) {
        const float4 (*sh)[32] = (warp == 0) ? shA : shF;
        float4 s = f4_add(f4_add(sh[0][lane], sh[1][lane]),
                          f4_add(sh[2][lane], sh[3][lane]));
        reinterpret_cast<float4*>(out + (size_t)g * (2 * EMB_DIM) + warp * EMB_DIM)[lane] = s;
    }
}

extern "C" void kernel_launch(void* const* d_in, const int* in_sizes, int n_in,
                              void* d_out, int out_size) {
    const float* x_atoms    = (const float*)d_in[0];
    const float* x_frags    = (const float*)d_in[1];
    const void*  batch      = d_in[2];
    const void*  frag_batch = d_in[3];
    float* out = (float*)d_out;

    const int n_atoms = in_sizes[2];
    const int n_frags = in_sizes[3];

    int* offs_atoms = nullptr;
    int* offs_frags = nullptr;
    cudaGetSymbolAddress((void**)&offs_atoms, g_offs_atoms);
    cudaGetSymbolAddress((void**)&offs_frags, g_offs_frags);

    const int chunks = ((n_atoms + 15) >> 4) + ((n_frags + 15) >> 4);
    const int T = 256;
    build_offsets_fused<<<(chunks + T - 1) / T, T>>>(batch, n_atoms, offs_atoms,
                                                     frag_batch, n_frags, offs_frags);
    fragnet_pool_kernel<<<NUM_GRAPHS, 128>>>(x_atoms, x_frags, out);
}